// round 14
// baseline (speedup 1.0000x reference)
#include <cuda_runtime.h>
#include <cuda_bf16.h>
#include <cstdint>

#define N_   8192
#define YD_  512
#define XD_  64
#define K_   16
#define S_   10
#define NS_  (N_*S_)
#define LOG2PI 1.8378770664093453

// ---- scratch (device globals) ----
__device__ float g_enc_mu[N_*XD_];
__device__ float g_enc_sig[N_*XD_];
__device__ __nv_bfloat16 g_xh[NS_*XD_];
__device__ double g_acc[4];   // 0: loss1, 1: loss2+3+4, 2: loss5
__device__ int g_cnt = 0;

__device__ __forceinline__ float softplus_f(float v) {
    return fmaxf(v, 0.0f) + log1pf(__expf(-fabsf(v)));
}
__device__ __forceinline__ float softplus_fast(float v) {
    return fmaxf(v, 0.0f) + __logf(1.0f + __expf(-fabsf(v)));
}
__device__ __forceinline__ void ldsm_x4(uint32_t* r, uint32_t addr) {
    asm volatile("ldmatrix.sync.aligned.m8n8.x4.shared.b16 {%0,%1,%2,%3}, [%4];"
        : "=r"(r[0]), "=r"(r[1]), "=r"(r[2]), "=r"(r[3]) : "r"(addr));
}
__device__ __forceinline__ void ldsm_x4_t(uint32_t* r, uint32_t addr) {
    asm volatile("ldmatrix.sync.aligned.m8n8.x4.trans.shared.b16 {%0,%1,%2,%3}, [%4];"
        : "=r"(r[0]), "=r"(r[1]), "=r"(r[2]), "=r"(r[3]) : "r"(addr));
}
#define MMA_BF16(C, A, B0, B1)                                          \
    asm volatile(                                                       \
        "mma.sync.aligned.m16n8k16.row.col.f32.bf16.bf16.f32 "          \
        "{%0,%1,%2,%3}, {%4,%5,%6,%7}, {%8,%9}, {%0,%1,%2,%3};"         \
        : "+f"(C[0]), "+f"(C[1]), "+f"(C[2]), "+f"(C[3])                \
        : "r"(A[0]), "r"(A[1]), "r"(A[2]), "r"(A[3]), "r"(B0), "r"(B1))

// ---- packed f32x2 helpers (Blackwell) ----
#define PACK2(o, v) \
    asm("mov.b64 %0, {%1, %1};" : "=l"(o) : "r"(__float_as_uint(v)))
#define FMA2(acc, a, b) \
    asm("fma.rn.f32x2 %0, %1, %2, %0;" : "+l"(acc) : "l"(a), "l"(b))
#define UNPACK2(lo, hi, v) \
    asm("mov.b64 {%0, %1}, %2;" : "=f"(lo), "=f"(hi) : "l"(v))

// ============================================================
// Kernel 1: bf16 encoder GEMM (R9 exact). BM=32, register-prefetch
// double buffering, grid 256.
// ============================================================
#define ESA 72
#define ESB 136

__global__ void __launch_bounds__(256) encoder_kernel(
    const float* __restrict__ Y,
    const float* __restrict__ We_mu, const float* __restrict__ be_mu,
    const float* __restrict__ We_sig, const float* __restrict__ be_sig)
{
    __shared__ __align__(16) __nv_bfloat16 sA[32 * ESA];
    __shared__ __align__(16) __nv_bfloat16 sB[64 * ESB];

    int tid = threadIdx.x;
    int warp = tid >> 5, lane = tid & 31;
    int row0 = blockIdx.x * 32;

    if (blockIdx.x == 0 && tid < 4) g_acc[tid] = 0.0;

    int ar  = tid >> 4, ac4 = (tid & 15) * 4;
    int ar2 = ar + 16;
    float4 rA[2];
    float4 rBf[8];

    #define ENC_LOAD(kc)                                                     \
    {   int k0 = (kc) * 64;                                                  \
        rA[0] = *(const float4*)(Y + (size_t)(row0 + ar) * YD_ + k0 + ac4);  \
        rA[1] = *(const float4*)(Y + (size_t)(row0 + ar2) * YD_ + k0 + ac4); \
        _Pragma("unroll")                                                    \
        for (int j = 0; j < 8; j++) {                                        \
            int i = tid + j * 256;                                           \
            int k = i >> 5, c4 = (i & 31) * 4;                               \
            const float* src = (c4 < 64) ? We_mu + (k0 + k) * XD_ + c4       \
                                         : We_sig + (k0 + k) * XD_ + (c4 - 64); \
            rBf[j] = *(const float4*)src;                                    \
        }                                                                    \
    }
    #define ENC_STORE()                                                     \
    {   *(__nv_bfloat162*)(sA + ar * ESA + ac4)      = __floats2bfloat162_rn(rA[0].x, rA[0].y); \
        *(__nv_bfloat162*)(sA + ar * ESA + ac4 + 2)  = __floats2bfloat162_rn(rA[0].z, rA[0].w); \
        *(__nv_bfloat162*)(sA + ar2 * ESA + ac4)     = __floats2bfloat162_rn(rA[1].x, rA[1].y); \
        *(__nv_bfloat162*)(sA + ar2 * ESA + ac4 + 2) = __floats2bfloat162_rn(rA[1].z, rA[1].w); \
        _Pragma("unroll")                                                    \
        for (int j = 0; j < 8; j++) {                                        \
            int i = tid + j * 256;                                           \
            int k = i >> 5, c4 = (i & 31) * 4;                               \
            *(__nv_bfloat162*)(sB + k * ESB + c4)     = __floats2bfloat162_rn(rBf[j].x, rBf[j].y); \
            *(__nv_bfloat162*)(sB + k * ESB + c4 + 2) = __floats2bfloat162_rn(rBf[j].z, rBf[j].w); \
        }                                                                    \
    }

    int mBase = (warp & 1) * 16;
    int nBase = (warp >> 1) * 32;
    int g = lane >> 2, tg = lane & 3;
    int mi = lane >> 3, ri = lane & 7;

    uint32_t aBase = (uint32_t)__cvta_generic_to_shared(sA);
    uint32_t bBase = (uint32_t)__cvta_generic_to_shared(sB);
    uint32_t aAddr = aBase +
        (((mBase + (mi & 1) * 8 + ri) * ESA) + (mi >> 1) * 8) * 2;
    uint32_t bAddr[2];
    #pragma unroll
    for (int p = 0; p < 2; p++)
        bAddr[p] = bBase +
            ((((mi & 1) * 8 + ri) * ESB) + nBase + p * 16 + (mi >> 1) * 8) * 2;

    float acc[4][4];
    #pragma unroll
    for (int nt = 0; nt < 4; nt++)
        #pragma unroll
        for (int r = 0; r < 4; r++) acc[nt][r] = 0.f;

    ENC_LOAD(0);
    for (int kc = 0; kc < 8; kc++) {
        ENC_STORE();
        __syncthreads();
        if (kc < 7) ENC_LOAD(kc + 1);
        #pragma unroll
        for (int ks = 0; ks < 4; ks++) {
            uint32_t a[4];
            ldsm_x4(a, aAddr + ks * 32);
            uint32_t b[2][4];
            ldsm_x4_t(b[0], bAddr[0] + ks * (16 * ESB * 2));
            ldsm_x4_t(b[1], bAddr[1] + ks * (16 * ESB * 2));
            #pragma unroll
            for (int nt = 0; nt < 4; nt++) {
                int p = nt >> 1, sel = (nt & 1) * 2;
                MMA_BF16(acc[nt], a, b[p][sel], b[p][sel + 1]);
            }
        }
        __syncthreads();
    }

    #pragma unroll
    for (int half = 0; half < 2; half++) {
        int row = row0 + mBase + g + half * 8;
        #pragma unroll
        for (int nt = 0; nt < 4; nt++) {
            #pragma unroll
            for (int p = 0; p < 2; p++) {
                int cl = nBase + nt * 8 + tg * 2 + p;
                float c = acc[nt][half * 2 + p];
                if (cl < 64) {
                    g_enc_mu[row * XD_ + cl] = c + be_mu[cl];
                } else {
                    int cc = cl - 64;
                    g_enc_sig[row * XD_ + cc] = softplus_f(c + be_sig[cc]) + 1e-3f;
                }
            }
        }
    }
}

// ============================================================
// Kernel 2: fused GMM + gumbel-softmax mixtures (R11 exact).
// f32x2-packed k-loop, one-rcp posterior.
// ============================================================
__global__ void __launch_bounds__(128) mixture_kernel(
    const float* __restrict__ phi_mus, const float* __restrict__ phi_sigs,
    const float* __restrict__ phi_logits,
    const float* __restrict__ theta_mus, const float* __restrict__ theta_sigs,
    const float* __restrict__ theta_logits,
    const float* __restrict__ u_noise, const float* __restrict__ eps_noise,
    const float* __restrict__ temperature)
{
    int tid = threadIdx.x;
    int sub = tid >> 6;
    int d = tid & 63;
    int n = blockIdx.x * 2 + sub;

    __shared__ float s_pmu[16 * 65], s_psg[16 * 65];
    __shared__ float s_tmu[16 * 65], s_tsg[16 * 65];
    __shared__ float em[2][64], es[2][64];
    __shared__ float lpi[16], lth[16];
    __shared__ float zl[2][16], zlp[2][16];
    __shared__ __align__(8) float s_z[2][16][12];   // [sub][k][s]
    __shared__ float sdt[2][S_];
    __shared__ float red[2][16][4];
    __shared__ float wred[2][2];
    __shared__ float sl5[2];

    for (int k = sub; k < 16; k += 2) {
        s_pmu[k * 65 + d] = phi_mus[k * XD_ + d];
        s_psg[k * 65 + d] = phi_sigs[k * XD_ + d];
        s_tmu[k * 65 + d] = theta_mus[k * XD_ + d];
        s_tsg[k * 65 + d] = theta_sigs[k * XD_ + d];
    }
    float emd = g_enc_mu[n * XD_ + d];
    float esd = g_enc_sig[n * XD_ + d];
    em[sub][d] = emd; es[sub][d] = esd;
    float iesd = 1.0f / esd;

    if (tid == 0) {
        float m = -1e30f;
        for (int k = 0; k < 16; k++) m = fmaxf(m, phi_logits[k]);
        float sm = 0.0f;
        for (int k = 0; k < 16; k++) sm += __expf(phi_logits[k] - m);
        float lse = m + __logf(sm);
        for (int k = 0; k < 16; k++) lpi[k] = phi_logits[k] - lse;
    }
    if (tid == 1) {
        float m = -1e30f;
        for (int k = 0; k < 16; k++) m = fmaxf(m, theta_logits[k]);
        float sm = 0.0f;
        for (int k = 0; k < 16; k++) sm += __expf(theta_logits[k] - m);
        float lse = m + __logf(sm);
        for (int k = 0; k < 16; k++) lth[k] = theta_logits[k] - lse;
    }
    __syncthreads();

    {
        int k = d >> 2, g4 = d & 3;
        float a = 0.0f, prod = 1.0f;
        #pragma unroll
        for (int i = 0; i < 16; i++) {
            int dd = g4 * 16 + i;
            float std = es[sub][dd] + s_psg[k * 65 + dd];
            float t = __fdividef(em[sub][dd] - s_pmu[k * 65 + dd], std);
            a += 0.5f * t * t;
            prod *= std;
        }
        red[sub][k][g4] = a + __logf(prod);
    }
    __syncthreads();
    if (d < 16)
        zl[sub][d] = lpi[d] - 0.5f * 64.0f * (float)LOG2PI
            - (red[sub][d][0] + red[sub][d][1] + red[sub][d][2] + red[sub][d][3]);
    __syncthreads();
    if (d == 0) {
        float m = -1e30f;
        for (int k = 0; k < 16; k++) m = fmaxf(m, zl[sub][k]);
        float sm = 0.0f;
        for (int k = 0; k < 16; k++) sm += __expf(zl[sub][k] - m);
        float lse = m + __logf(sm);
        for (int k = 0; k < 16; k++) zlp[sub][k] = zl[sub][k] - lse;
        float s2 = 0.0f;
        for (int k = 0; k < 16; k++) s2 += __expf(zlp[sub][k]);
        sl5[sub] = __logf(s2);
    }
    __syncthreads();

    float invT = 1.0f / temperature[0];
    if (d < S_) {
        int s = d;
        const float* urow = u_noise + (size_t)n * (S_ * K_) + s * K_;
        float v[16];
        float m = -1e30f;
        #pragma unroll
        for (int k = 0; k < 16; k++) {
            float gg = -__logf(-__logf(urow[k]));
            v[k] = (zlp[sub][k] + gg) * invT;
            m = fmaxf(m, v[k]);
        }
        float sm = 0.0f;
        #pragma unroll
        for (int k = 0; k < 16; k++) { v[k] = __expf(v[k] - m); sm += v[k]; }
        float inv = 1.0f / sm;
        float dt = 0.0f;
        #pragma unroll
        for (int k = 0; k < 16; k++) {
            float z = v[k] * inv;
            s_z[sub][k][s] = z;
            dt = fmaf(z, lth[k] - zlp[sub][k], dt);
        }
        sdt[sub][s] = dt;
    }
    __syncthreads();

    unsigned long long aM[5], aS[5], aTm[5], aTs[5], aPm[5], aPs[5];
    #pragma unroll
    for (int j = 0; j < 5; j++) {
        aM[j] = 0ULL; aS[j] = 0ULL; aTm[j] = 0ULL;
        aTs[j] = 0ULL; aPm[j] = 0ULL; aPs[j] = 0ULL;
    }
    #pragma unroll
    for (int k = 0; k < 16; k++) {
        float pmu  = s_pmu[k * 65 + d];
        float psig = s_psg[k * 65 + d];
        float tmu  = s_tmu[k * 65 + d];
        float tsig = s_tsg[k * 65 + d];
        float r  = __fdividef(1.0f, psig + esd);
        float st = psig * esd * r;
        float w  = psig * r;
        float mut = fmaf(w, emd - pmu, pmu);
        unsigned long long bM, bS, bTm, bTs, bPm, bPs;
        PACK2(bM, mut);  PACK2(bS, st);   PACK2(bTm, tmu);
        PACK2(bTs, tsig); PACK2(bPm, pmu); PACK2(bPs, psig);
        #pragma unroll
        for (int j = 0; j < 5; j++) {
            unsigned long long zz =
                *(const unsigned long long*)&s_z[sub][k][j * 2];
            FMA2(aM[j], zz, bM);
            FMA2(aS[j], zz, bS);
            FMA2(aTm[j], zz, bTm);
            FMA2(aTs[j], zz, bTs);
            FMA2(aPm[j], zz, bPm);
            FMA2(aPs[j], zz, bPs);
        }
    }
    float ms[S_], ssg[S_], tm[S_], tsg[S_], pm[S_], psg[S_];
    #pragma unroll
    for (int j = 0; j < 5; j++) {
        UNPACK2(ms[2*j],  ms[2*j+1],  aM[j]);
        UNPACK2(ssg[2*j], ssg[2*j+1], aS[j]);
        UNPACK2(tm[2*j],  tm[2*j+1],  aTm[j]);
        UNPACK2(tsg[2*j], tsg[2*j+1], aTs[j]);
        UNPACK2(pm[2*j],  pm[2*j+1],  aPm[j]);
        UNPACK2(psg[2*j], psg[2*j+1], aPs[j]);
    }

    float lacc = 0.0f;
    float lp = 1.0f;
    #pragma unroll
    for (int s = 0; s < S_; s++) {
        int row = n * S_ + s;
        float x = fmaf(sqrtf(ssg[s]), eps_noise[(size_t)row * XD_ + d], ms[s]);
        g_xh[(size_t)row * XD_ + d] = __float2bfloat16_rn(x);
        float te = (x - emd) * iesd;
        float rt = __fdividef(1.0f, tsg[s]);
        float rp = __fdividef(1.0f, psg[s]);
        float tt = (x - tm[s]) * rt;
        float tp = (x - pm[s]) * rp;
        lacc += 0.5f * (te * te - tt * tt + tp * tp);
        lp *= psg[s] * rt;
    }
    lacc += __logf(lp) + (float)S_ * __logf(esd);

    #pragma unroll
    for (int o = 16; o > 0; o >>= 1)
        lacc += __shfl_down_sync(0xffffffffu, lacc, o);
    if ((tid & 31) == 0) wred[sub][(tid >> 5) & 1] = lacc;
    __syncthreads();
    if (d == 0) {
        float dts = 0.0f;
        #pragma unroll
        for (int s = 0; s < S_; s++) dts += sdt[sub][s];
        double tot = (double)(wred[sub][0] + wred[sub][1]) + (double)dts;
        atomicAdd(&g_acc[1], tot);
        atomicAdd(&g_acc[2], (double)sl5[sub]);
    }
}

// ============================================================
// Kernel 3: bf16 decoder GEMMs fused with loss1 (R11 base) +
// fused finalize. ONLY change vs R11: pair-reciprocal epilogue
// (one MUFU rcp per 2 elements instead of 2).
// ============================================================
#define SA 72
#define SB 72
#define DBM 128
#define DEC_GRID ((NS_/DBM)*(YD_/64))

__global__ void __launch_bounds__(256) decoder_kernel(
    const float* __restrict__ Y,
    const float* __restrict__ Wd_mu, const float* __restrict__ bd_mu,
    const float* __restrict__ Wd_sig, const float* __restrict__ bd_sig,
    float* __restrict__ out)
{
    __shared__ __align__(16) __nv_bfloat16 sA[DBM * SA];
    __shared__ __align__(16) __nv_bfloat16 sBm[64 * SB];
    __shared__ __align__(16) __nv_bfloat16 sBs[64 * SB];
    __shared__ float sbm[64], sbs[64];
    __shared__ float warp_red[8];

    int tid = threadIdx.x;
    int warp = tid >> 5, lane = tid & 31;
    int row0 = blockIdx.x * DBM;
    int col0 = blockIdx.y * 64;

    const __nv_bfloat16* gx = g_xh + (size_t)row0 * XD_;
    #pragma unroll
    for (int i = tid; i < DBM * 8; i += 256) {
        int r = i >> 3, c8 = (i & 7) * 8;
        *(uint4*)(sA + r * SA + c8) = *(const uint4*)(gx + r * XD_ + c8);
    }
    #pragma unroll
    for (int i = tid; i < 64 * 16; i += 256) {
        int k = i >> 4, c4 = (i & 15) * 4;
        float4 vm = *(const float4*)(Wd_mu + k * YD_ + col0 + c4);
        float4 vs = *(const float4*)(Wd_sig + k * YD_ + col0 + c4);
        *(__nv_bfloat162*)(sBm + k * SB + c4)     = __floats2bfloat162_rn(vm.x, vm.y);
        *(__nv_bfloat162*)(sBm + k * SB + c4 + 2) = __floats2bfloat162_rn(vm.z, vm.w);
        *(__nv_bfloat162*)(sBs + k * SB + c4)     = __floats2bfloat162_rn(vs.x, vs.y);
        *(__nv_bfloat162*)(sBs + k * SB + c4 + 2) = __floats2bfloat162_rn(vs.z, vs.w);
    }
    if (tid < 64) {
        sbm[tid] = bd_mu[col0 + tid];
        sbs[tid] = bd_sig[col0 + tid];
    }
    __syncthreads();

    int wm = warp & 3;
    int wn = warp >> 2;
    int mBase = wm * 32;
    int nBase = wn * 32;
    int g = lane >> 2, tg = lane & 3;
    int mi = lane >> 3, ri = lane & 7;

    uint32_t aBase  = (uint32_t)__cvta_generic_to_shared(sA);
    uint32_t bmBase = (uint32_t)__cvta_generic_to_shared(sBm);
    uint32_t bsBase = (uint32_t)__cvta_generic_to_shared(sBs);
    uint32_t aAddr[2];
    #pragma unroll
    for (int mt = 0; mt < 2; mt++)
        aAddr[mt] = aBase +
            (((mBase + mt * 16 + (mi & 1) * 8 + ri) * SA) + (mi >> 1) * 8) * 2;
    uint32_t bmAddr[2], bsAddr[2];
    #pragma unroll
    for (int p = 0; p < 2; p++) {
        uint32_t off = (((mi & 1) * 8 + ri) * SB + nBase + p * 16 + (mi >> 1) * 8) * 2;
        bmAddr[p] = bmBase + off;
        bsAddr[p] = bsBase + off;
    }

    float cm[2][4][4], cs[2][4][4];
    #pragma unroll
    for (int mt = 0; mt < 2; mt++)
        #pragma unroll
        for (int nt = 0; nt < 4; nt++)
            #pragma unroll
            for (int r = 0; r < 4; r++) { cm[mt][nt][r] = 0.f; cs[mt][nt][r] = 0.f; }

    #pragma unroll
    for (int ks = 0; ks < 4; ks++) {
        uint32_t a[2][4];
        ldsm_x4(a[0], aAddr[0] + ks * 32);
        ldsm_x4(a[1], aAddr[1] + ks * 32);
        uint32_t bm[2][4], bs[2][4];
        #pragma unroll
        for (int p = 0; p < 2; p++) {
            ldsm_x4_t(bm[p], bmAddr[p] + ks * (16 * SB * 2));
            ldsm_x4_t(bs[p], bsAddr[p] + ks * (16 * SB * 2));
        }
        #pragma unroll
        for (int nt = 0; nt < 4; nt++) {
            int p = nt >> 1, sel = (nt & 1) * 2;
            #pragma unroll
            for (int mt = 0; mt < 2; mt++) {
                MMA_BF16(cm[mt][nt], a[mt], bm[p][sel], bm[p][sel + 1]);
                MMA_BF16(cs[mt][nt], a[mt], bs[p][sel], bs[p][sel + 1]);
            }
        }
    }

    // --- fused loss1 epilogue: pair-reciprocal (1 rcp / 2 elems) ---
    float part = 0.0f;
    #pragma unroll
    for (int mt = 0; mt < 2; mt++) {
        #pragma unroll
        for (int half = 0; half < 2; half++) {
            int row = row0 + mBase + mt * 16 + g + half * 8;
            int n = row / S_;
            const float* yrow = Y + (size_t)n * YD_ + col0;
            float prod = 1.0f;
            #pragma unroll
            for (int nt = 0; nt < 4; nt++) {
                int r0 = half * 2, r1 = half * 2 + 1;
                int cl0 = nBase + nt * 8 + tg * 2;
                int cl1 = cl0 + 1;
                float mu0 = cm[mt][nt][r0] + sbm[cl0];
                float mu1 = cm[mt][nt][r1] + sbm[cl1];
                float sg0 = softplus_fast(cs[mt][nt][r0] + sbs[cl0]) + 1e-3f;
                float sg1 = softplus_fast(cs[mt][nt][r1] + sbs[cl1]) + 1e-3f;
                float d0 = yrow[cl0] - mu0;
                float d1 = yrow[cl1] - mu1;
                float p01 = sg0 * sg1;
                float r01 = __fdividef(1.0f, p01);
                float t0 = d0 * sg1 * r01;
                float t1 = d1 * sg0 * r01;
                part -= 0.5f * (t0 * t0 + t1 * t1);
                prod *= p01;
            }
            part -= __logf(prod);
        }
    }
    #pragma unroll
    for (int o = 16; o > 0; o >>= 1)
        part += __shfl_down_sync(0xffffffffu, part, o);
    if (lane == 0) warp_red[warp] = part;
    __syncthreads();
    if (tid == 0) {
        float tot = 0.0f;
        #pragma unroll
        for (int w = 0; w < 8; w++) tot += warp_red[w];
        atomicAdd(&g_acc[0], (double)tot);
        __threadfence();
        int ticket = atomicAdd(&g_cnt, 1);
        if (ticket == DEC_GRID - 1) {
            g_cnt = 0;
            double NSd = (double)NS_;
            double L1   = g_acc[0] - 0.5 * (double)YD_ * LOG2PI * NSd;
            double L234 = g_acc[1] + 0.5 * (double)XD_ * LOG2PI * NSd;
            double totl = (L1 + L234) / (double)S_ + g_acc[2];
            out[0] = (float)(-totl);
        }
    }
}

extern "C" void kernel_launch(void* const* d_in, const int* in_sizes, int n_in,
                              void* d_out, int out_size)
{
    const float* Y            = (const float*)d_in[0];
    const float* We_mu        = (const float*)d_in[1];
    const float* be_mu        = (const float*)d_in[2];
    const float* We_sig       = (const float*)d_in[3];
    const float* be_sig       = (const float*)d_in[4];
    const float* Wd_mu        = (const float*)d_in[5];
    const float* bd_mu        = (const float*)d_in[6];
    const float* Wd_sig       = (const float*)d_in[7];
    const float* bd_sig       = (const float*)d_in[8];
    const float* phi_mus      = (const float*)d_in[9];
    const float* phi_sigs     = (const float*)d_in[10];
    const float* phi_logits   = (const float*)d_in[11];
    const float* theta_mus    = (const float*)d_in[12];
    const float* theta_sigs   = (const float*)d_in[13];
    const float* theta_logits = (const float*)d_in[14];
    const float* u_noise      = (const float*)d_in[15];
    const float* eps_noise    = (const float*)d_in[16];
    const float* temperature  = (const float*)d_in[17];

    encoder_kernel<<<N_ / 32, 256>>>(Y, We_mu, be_mu, We_sig, be_sig);
    mixture_kernel<<<N_ / 2, 128>>>(phi_mus, phi_sigs, phi_logits,
                                    theta_mus, theta_sigs, theta_logits,
                                    u_noise, eps_noise, temperature);
    decoder_kernel<<<dim3(NS_ / DBM, YD_ / 64), 256>>>(Y, Wd_mu, bd_mu,
                                                       Wd_sig, bd_sig,
                                                       (float*)d_out);
}

// round 15
// speedup vs baseline: 1.5164x; 1.5164x over previous
#include <cuda_runtime.h>
#include <cuda_bf16.h>
#include <cstdint>

#define N_   8192
#define YD_  512
#define XD_  64
#define K_   16
#define S_   10
#define NS_  (N_*S_)
#define LOG2PI 1.8378770664093453

// ---- scratch (device globals) ----
__device__ float g_enc_mu[N_*XD_];
__device__ float g_enc_sig[N_*XD_];
__device__ __nv_bfloat16 g_xh[NS_*XD_];
__device__ double g_acc[4];   // 0: loss1, 1: loss2+3+4, 2: loss5
__device__ int g_cnt = 0;

__device__ __forceinline__ float softplus_f(float v) {
    return fmaxf(v, 0.0f) + log1pf(__expf(-fabsf(v)));
}
__device__ __forceinline__ float softplus_fast(float v) {
    return fmaxf(v, 0.0f) + __logf(1.0f + __expf(-fabsf(v)));
}
__device__ __forceinline__ void ldsm_x4(uint32_t* r, uint32_t addr) {
    asm volatile("ldmatrix.sync.aligned.m8n8.x4.shared.b16 {%0,%1,%2,%3}, [%4];"
        : "=r"(r[0]), "=r"(r[1]), "=r"(r[2]), "=r"(r[3]) : "r"(addr));
}
__device__ __forceinline__ void ldsm_x4_t(uint32_t* r, uint32_t addr) {
    asm volatile("ldmatrix.sync.aligned.m8n8.x4.trans.shared.b16 {%0,%1,%2,%3}, [%4];"
        : "=r"(r[0]), "=r"(r[1]), "=r"(r[2]), "=r"(r[3]) : "r"(addr));
}
#define MMA_BF16(C, A, B0, B1)                                          \
    asm volatile(                                                       \
        "mma.sync.aligned.m16n8k16.row.col.f32.bf16.bf16.f32 "          \
        "{%0,%1,%2,%3}, {%4,%5,%6,%7}, {%8,%9}, {%0,%1,%2,%3};"         \
        : "+f"(C[0]), "+f"(C[1]), "+f"(C[2]), "+f"(C[3])                \
        : "r"(A[0]), "r"(A[1]), "r"(A[2]), "r"(A[3]), "r"(B0), "r"(B1))

// ---- packed f32x2 helpers (Blackwell) ----
#define PACK2(o, v) \
    asm("mov.b64 %0, {%1, %1};" : "=l"(o) : "r"(__float_as_uint(v)))
#define FMA2(acc, a, b) \
    asm("fma.rn.f32x2 %0, %1, %2, %0;" : "+l"(acc) : "l"(a), "l"(b))
#define UNPACK2(lo, hi, v) \
    asm("mov.b64 {%0, %1}, %2;" : "=f"(lo), "=f"(hi) : "l"(v))

// ============================================================
// Kernel 1: bf16 encoder GEMM (R9 exact). BM=32, register-prefetch
// double buffering, grid 256.
// ============================================================
#define ESA 72
#define ESB 136

__global__ void __launch_bounds__(256) encoder_kernel(
    const float* __restrict__ Y,
    const float* __restrict__ We_mu, const float* __restrict__ be_mu,
    const float* __restrict__ We_sig, const float* __restrict__ be_sig)
{
    __shared__ __align__(16) __nv_bfloat16 sA[32 * ESA];
    __shared__ __align__(16) __nv_bfloat16 sB[64 * ESB];

    int tid = threadIdx.x;
    int warp = tid >> 5, lane = tid & 31;
    int row0 = blockIdx.x * 32;

    if (blockIdx.x == 0 && tid < 4) g_acc[tid] = 0.0;

    int ar  = tid >> 4, ac4 = (tid & 15) * 4;
    int ar2 = ar + 16;
    float4 rA[2];
    float4 rBf[8];

    #define ENC_LOAD(kc)                                                     \
    {   int k0 = (kc) * 64;                                                  \
        rA[0] = *(const float4*)(Y + (size_t)(row0 + ar) * YD_ + k0 + ac4);  \
        rA[1] = *(const float4*)(Y + (size_t)(row0 + ar2) * YD_ + k0 + ac4); \
        _Pragma("unroll")                                                    \
        for (int j = 0; j < 8; j++) {                                        \
            int i = tid + j * 256;                                           \
            int k = i >> 5, c4 = (i & 31) * 4;                               \
            const float* src = (c4 < 64) ? We_mu + (k0 + k) * XD_ + c4       \
                                         : We_sig + (k0 + k) * XD_ + (c4 - 64); \
            rBf[j] = *(const float4*)src;                                    \
        }                                                                    \
    }
    #define ENC_STORE()                                                     \
    {   *(__nv_bfloat162*)(sA + ar * ESA + ac4)      = __floats2bfloat162_rn(rA[0].x, rA[0].y); \
        *(__nv_bfloat162*)(sA + ar * ESA + ac4 + 2)  = __floats2bfloat162_rn(rA[0].z, rA[0].w); \
        *(__nv_bfloat162*)(sA + ar2 * ESA + ac4)     = __floats2bfloat162_rn(rA[1].x, rA[1].y); \
        *(__nv_bfloat162*)(sA + ar2 * ESA + ac4 + 2) = __floats2bfloat162_rn(rA[1].z, rA[1].w); \
        _Pragma("unroll")                                                    \
        for (int j = 0; j < 8; j++) {                                        \
            int i = tid + j * 256;                                           \
            int k = i >> 5, c4 = (i & 31) * 4;                               \
            *(__nv_bfloat162*)(sB + k * ESB + c4)     = __floats2bfloat162_rn(rBf[j].x, rBf[j].y); \
            *(__nv_bfloat162*)(sB + k * ESB + c4 + 2) = __floats2bfloat162_rn(rBf[j].z, rBf[j].w); \
        }                                                                    \
    }

    int mBase = (warp & 1) * 16;
    int nBase = (warp >> 1) * 32;
    int g = lane >> 2, tg = lane & 3;
    int mi = lane >> 3, ri = lane & 7;

    uint32_t aBase = (uint32_t)__cvta_generic_to_shared(sA);
    uint32_t bBase = (uint32_t)__cvta_generic_to_shared(sB);
    uint32_t aAddr = aBase +
        (((mBase + (mi & 1) * 8 + ri) * ESA) + (mi >> 1) * 8) * 2;
    uint32_t bAddr[2];
    #pragma unroll
    for (int p = 0; p < 2; p++)
        bAddr[p] = bBase +
            ((((mi & 1) * 8 + ri) * ESB) + nBase + p * 16 + (mi >> 1) * 8) * 2;

    float acc[4][4];
    #pragma unroll
    for (int nt = 0; nt < 4; nt++)
        #pragma unroll
        for (int r = 0; r < 4; r++) acc[nt][r] = 0.f;

    ENC_LOAD(0);
    for (int kc = 0; kc < 8; kc++) {
        ENC_STORE();
        __syncthreads();
        if (kc < 7) ENC_LOAD(kc + 1);
        #pragma unroll
        for (int ks = 0; ks < 4; ks++) {
            uint32_t a[4];
            ldsm_x4(a, aAddr + ks * 32);
            uint32_t b[2][4];
            ldsm_x4_t(b[0], bAddr[0] + ks * (16 * ESB * 2));
            ldsm_x4_t(b[1], bAddr[1] + ks * (16 * ESB * 2));
            #pragma unroll
            for (int nt = 0; nt < 4; nt++) {
                int p = nt >> 1, sel = (nt & 1) * 2;
                MMA_BF16(acc[nt], a, b[p][sel], b[p][sel + 1]);
            }
        }
        __syncthreads();
    }

    #pragma unroll
    for (int half = 0; half < 2; half++) {
        int row = row0 + mBase + g + half * 8;
        #pragma unroll
        for (int nt = 0; nt < 4; nt++) {
            #pragma unroll
            for (int p = 0; p < 2; p++) {
                int cl = nBase + nt * 8 + tg * 2 + p;
                float c = acc[nt][half * 2 + p];
                if (cl < 64) {
                    g_enc_mu[row * XD_ + cl] = c + be_mu[cl];
                } else {
                    int cc = cl - 64;
                    g_enc_sig[row * XD_ + cc] = softplus_f(c + be_sig[cc]) + 1e-3f;
                }
            }
        }
    }
}

// ============================================================
// Kernel 2: fused GMM + gumbel-softmax mixtures (R11 exact).
// f32x2-packed k-loop, one-rcp posterior.
// ============================================================
__global__ void __launch_bounds__(128) mixture_kernel(
    const float* __restrict__ phi_mus, const float* __restrict__ phi_sigs,
    const float* __restrict__ phi_logits,
    const float* __restrict__ theta_mus, const float* __restrict__ theta_sigs,
    const float* __restrict__ theta_logits,
    const float* __restrict__ u_noise, const float* __restrict__ eps_noise,
    const float* __restrict__ temperature)
{
    int tid = threadIdx.x;
    int sub = tid >> 6;
    int d = tid & 63;
    int n = blockIdx.x * 2 + sub;

    __shared__ float s_pmu[16 * 65], s_psg[16 * 65];
    __shared__ float s_tmu[16 * 65], s_tsg[16 * 65];
    __shared__ float em[2][64], es[2][64];
    __shared__ float lpi[16], lth[16];
    __shared__ float zl[2][16], zlp[2][16];
    __shared__ __align__(8) float s_z[2][16][12];   // [sub][k][s]
    __shared__ float sdt[2][S_];
    __shared__ float red[2][16][4];
    __shared__ float wred[2][2];
    __shared__ float sl5[2];

    for (int k = sub; k < 16; k += 2) {
        s_pmu[k * 65 + d] = phi_mus[k * XD_ + d];
        s_psg[k * 65 + d] = phi_sigs[k * XD_ + d];
        s_tmu[k * 65 + d] = theta_mus[k * XD_ + d];
        s_tsg[k * 65 + d] = theta_sigs[k * XD_ + d];
    }
    float emd = g_enc_mu[n * XD_ + d];
    float esd = g_enc_sig[n * XD_ + d];
    em[sub][d] = emd; es[sub][d] = esd;
    float iesd = 1.0f / esd;

    if (tid == 0) {
        float m = -1e30f;
        for (int k = 0; k < 16; k++) m = fmaxf(m, phi_logits[k]);
        float sm = 0.0f;
        for (int k = 0; k < 16; k++) sm += __expf(phi_logits[k] - m);
        float lse = m + __logf(sm);
        for (int k = 0; k < 16; k++) lpi[k] = phi_logits[k] - lse;
    }
    if (tid == 1) {
        float m = -1e30f;
        for (int k = 0; k < 16; k++) m = fmaxf(m, theta_logits[k]);
        float sm = 0.0f;
        for (int k = 0; k < 16; k++) sm += __expf(theta_logits[k] - m);
        float lse = m + __logf(sm);
        for (int k = 0; k < 16; k++) lth[k] = theta_logits[k] - lse;
    }
    __syncthreads();

    {
        int k = d >> 2, g4 = d & 3;
        float a = 0.0f, prod = 1.0f;
        #pragma unroll
        for (int i = 0; i < 16; i++) {
            int dd = g4 * 16 + i;
            float std = es[sub][dd] + s_psg[k * 65 + dd];
            float t = __fdividef(em[sub][dd] - s_pmu[k * 65 + dd], std);
            a += 0.5f * t * t;
            prod *= std;
        }
        red[sub][k][g4] = a + __logf(prod);
    }
    __syncthreads();
    if (d < 16)
        zl[sub][d] = lpi[d] - 0.5f * 64.0f * (float)LOG2PI
            - (red[sub][d][0] + red[sub][d][1] + red[sub][d][2] + red[sub][d][3]);
    __syncthreads();
    if (d == 0) {
        float m = -1e30f;
        for (int k = 0; k < 16; k++) m = fmaxf(m, zl[sub][k]);
        float sm = 0.0f;
        for (int k = 0; k < 16; k++) sm += __expf(zl[sub][k] - m);
        float lse = m + __logf(sm);
        for (int k = 0; k < 16; k++) zlp[sub][k] = zl[sub][k] - lse;
        float s2 = 0.0f;
        for (int k = 0; k < 16; k++) s2 += __expf(zlp[sub][k]);
        sl5[sub] = __logf(s2);
    }
    __syncthreads();

    float invT = 1.0f / temperature[0];
    if (d < S_) {
        int s = d;
        const float* urow = u_noise + (size_t)n * (S_ * K_) + s * K_;
        float v[16];
        float m = -1e30f;
        #pragma unroll
        for (int k = 0; k < 16; k++) {
            float gg = -__logf(-__logf(urow[k]));
            v[k] = (zlp[sub][k] + gg) * invT;
            m = fmaxf(m, v[k]);
        }
        float sm = 0.0f;
        #pragma unroll
        for (int k = 0; k < 16; k++) { v[k] = __expf(v[k] - m); sm += v[k]; }
        float inv = 1.0f / sm;
        float dt = 0.0f;
        #pragma unroll
        for (int k = 0; k < 16; k++) {
            float z = v[k] * inv;
            s_z[sub][k][s] = z;
            dt = fmaf(z, lth[k] - zlp[sub][k], dt);
        }
        sdt[sub][s] = dt;
    }
    __syncthreads();

    unsigned long long aM[5], aS[5], aTm[5], aTs[5], aPm[5], aPs[5];
    #pragma unroll
    for (int j = 0; j < 5; j++) {
        aM[j] = 0ULL; aS[j] = 0ULL; aTm[j] = 0ULL;
        aTs[j] = 0ULL; aPm[j] = 0ULL; aPs[j] = 0ULL;
    }
    #pragma unroll
    for (int k = 0; k < 16; k++) {
        float pmu  = s_pmu[k * 65 + d];
        float psig = s_psg[k * 65 + d];
        float tmu  = s_tmu[k * 65 + d];
        float tsig = s_tsg[k * 65 + d];
        float r  = __fdividef(1.0f, psig + esd);
        float st = psig * esd * r;
        float w  = psig * r;
        float mut = fmaf(w, emd - pmu, pmu);
        unsigned long long bM, bS, bTm, bTs, bPm, bPs;
        PACK2(bM, mut);  PACK2(bS, st);   PACK2(bTm, tmu);
        PACK2(bTs, tsig); PACK2(bPm, pmu); PACK2(bPs, psig);
        #pragma unroll
        for (int j = 0; j < 5; j++) {
            unsigned long long zz =
                *(const unsigned long long*)&s_z[sub][k][j * 2];
            FMA2(aM[j], zz, bM);
            FMA2(aS[j], zz, bS);
            FMA2(aTm[j], zz, bTm);
            FMA2(aTs[j], zz, bTs);
            FMA2(aPm[j], zz, bPm);
            FMA2(aPs[j], zz, bPs);
        }
    }
    float ms[S_], ssg[S_], tm[S_], tsg[S_], pm[S_], psg[S_];
    #pragma unroll
    for (int j = 0; j < 5; j++) {
        UNPACK2(ms[2*j],  ms[2*j+1],  aM[j]);
        UNPACK2(ssg[2*j], ssg[2*j+1], aS[j]);
        UNPACK2(tm[2*j],  tm[2*j+1],  aTm[j]);
        UNPACK2(tsg[2*j], tsg[2*j+1], aTs[j]);
        UNPACK2(pm[2*j],  pm[2*j+1],  aPm[j]);
        UNPACK2(psg[2*j], psg[2*j+1], aPs[j]);
    }

    float lacc = 0.0f;
    float lp = 1.0f;
    #pragma unroll
    for (int s = 0; s < S_; s++) {
        int row = n * S_ + s;
        float x = fmaf(sqrtf(ssg[s]), eps_noise[(size_t)row * XD_ + d], ms[s]);
        g_xh[(size_t)row * XD_ + d] = __float2bfloat16_rn(x);
        float te = (x - emd) * iesd;
        float rt = __fdividef(1.0f, tsg[s]);
        float rp = __fdividef(1.0f, psg[s]);
        float tt = (x - tm[s]) * rt;
        float tp = (x - pm[s]) * rp;
        lacc += 0.5f * (te * te - tt * tt + tp * tp);
        lp *= psg[s] * rt;
    }
    lacc += __logf(lp) + (float)S_ * __logf(esd);

    #pragma unroll
    for (int o = 16; o > 0; o >>= 1)
        lacc += __shfl_down_sync(0xffffffffu, lacc, o);
    if ((tid & 31) == 0) wred[sub][(tid >> 5) & 1] = lacc;
    __syncthreads();
    if (d == 0) {
        float dts = 0.0f;
        #pragma unroll
        for (int s = 0; s < S_; s++) dts += sdt[sub][s];
        double tot = (double)(wred[sub][0] + wred[sub][1]) + (double)dts;
        atomicAdd(&g_acc[1], tot);
        atomicAdd(&g_acc[2], (double)sl5[sub]);
    }
}

// ============================================================
// Kernel 3: bf16 decoder GEMMs fused with loss1 (R11 exact) +
// fused finalize ticket.
// ============================================================
#define SA 72
#define SB 72
#define DBM 128
#define DEC_GRID ((NS_/DBM)*(YD_/64))

__global__ void __launch_bounds__(256) decoder_kernel(
    const float* __restrict__ Y,
    const float* __restrict__ Wd_mu, const float* __restrict__ bd_mu,
    const float* __restrict__ Wd_sig, const float* __restrict__ bd_sig,
    float* __restrict__ out)
{
    __shared__ __align__(16) __nv_bfloat16 sA[DBM * SA];
    __shared__ __align__(16) __nv_bfloat16 sBm[64 * SB];
    __shared__ __align__(16) __nv_bfloat16 sBs[64 * SB];
    __shared__ float sbm[64], sbs[64];
    __shared__ float warp_red[8];

    int tid = threadIdx.x;
    int warp = tid >> 5, lane = tid & 31;
    int row0 = blockIdx.x * DBM;
    int col0 = blockIdx.y * 64;

    const __nv_bfloat16* gx = g_xh + (size_t)row0 * XD_;
    #pragma unroll
    for (int i = tid; i < DBM * 8; i += 256) {
        int r = i >> 3, c8 = (i & 7) * 8;
        *(uint4*)(sA + r * SA + c8) = *(const uint4*)(gx + r * XD_ + c8);
    }
    #pragma unroll
    for (int i = tid; i < 64 * 16; i += 256) {
        int k = i >> 4, c4 = (i & 15) * 4;
        float4 vm = *(const float4*)(Wd_mu + k * YD_ + col0 + c4);
        float4 vs = *(const float4*)(Wd_sig + k * YD_ + col0 + c4);
        *(__nv_bfloat162*)(sBm + k * SB + c4)     = __floats2bfloat162_rn(vm.x, vm.y);
        *(__nv_bfloat162*)(sBm + k * SB + c4 + 2) = __floats2bfloat162_rn(vm.z, vm.w);
        *(__nv_bfloat162*)(sBs + k * SB + c4)     = __floats2bfloat162_rn(vs.x, vs.y);
        *(__nv_bfloat162*)(sBs + k * SB + c4 + 2) = __floats2bfloat162_rn(vs.z, vs.w);
    }
    if (tid < 64) {
        sbm[tid] = bd_mu[col0 + tid];
        sbs[tid] = bd_sig[col0 + tid];
    }
    __syncthreads();

    int wm = warp & 3;
    int wn = warp >> 2;
    int mBase = wm * 32;
    int nBase = wn * 32;
    int g = lane >> 2, tg = lane & 3;
    int mi = lane >> 3, ri = lane & 7;

    uint32_t aBase  = (uint32_t)__cvta_generic_to_shared(sA);
    uint32_t bmBase = (uint32_t)__cvta_generic_to_shared(sBm);
    uint32_t bsBase = (uint32_t)__cvta_generic_to_shared(sBs);
    uint32_t aAddr[2];
    #pragma unroll
    for (int mt = 0; mt < 2; mt++)
        aAddr[mt] = aBase +
            (((mBase + mt * 16 + (mi & 1) * 8 + ri) * SA) + (mi >> 1) * 8) * 2;
    uint32_t bmAddr[2], bsAddr[2];
    #pragma unroll
    for (int p = 0; p < 2; p++) {
        uint32_t off = (((mi & 1) * 8 + ri) * SB + nBase + p * 16 + (mi >> 1) * 8) * 2;
        bmAddr[p] = bmBase + off;
        bsAddr[p] = bsBase + off;
    }

    float cm[2][4][4], cs[2][4][4];
    #pragma unroll
    for (int mt = 0; mt < 2; mt++)
        #pragma unroll
        for (int nt = 0; nt < 4; nt++)
            #pragma unroll
            for (int r = 0; r < 4; r++) { cm[mt][nt][r] = 0.f; cs[mt][nt][r] = 0.f; }

    #pragma unroll
    for (int ks = 0; ks < 4; ks++) {
        uint32_t a[2][4];
        ldsm_x4(a[0], aAddr[0] + ks * 32);
        ldsm_x4(a[1], aAddr[1] + ks * 32);
        uint32_t bm[2][4], bs[2][4];
        #pragma unroll
        for (int p = 0; p < 2; p++) {
            ldsm_x4_t(bm[p], bmAddr[p] + ks * (16 * SB * 2));
            ldsm_x4_t(bs[p], bsAddr[p] + ks * (16 * SB * 2));
        }
        #pragma unroll
        for (int nt = 0; nt < 4; nt++) {
            int p = nt >> 1, sel = (nt & 1) * 2;
            #pragma unroll
            for (int mt = 0; mt < 2; mt++) {
                MMA_BF16(cm[mt][nt], a[mt], bm[p][sel], bm[p][sel + 1]);
                MMA_BF16(cs[mt][nt], a[mt], bs[p][sel], bs[p][sel + 1]);
            }
        }
    }

    float part = 0.0f;
    #pragma unroll
    for (int mt = 0; mt < 2; mt++) {
        #pragma unroll
        for (int half = 0; half < 2; half++) {
            int row = row0 + mBase + mt * 16 + g + half * 8;
            int n = row / S_;
            const float* yrow = Y + (size_t)n * YD_ + col0;
            float prod = 1.0f;
            #pragma unroll
            for (int nt = 0; nt < 4; nt++) {
                #pragma unroll
                for (int p = 0; p < 2; p++) {
                    int r = half * 2 + p;
                    int cl = nBase + nt * 8 + tg * 2 + p;
                    float mu = cm[mt][nt][r] + sbm[cl];
                    float sg = softplus_fast(cs[mt][nt][r] + sbs[cl]) + 1e-3f;
                    float t = __fdividef(yrow[cl] - mu, sg);
                    part -= 0.5f * t * t;
                    prod *= sg;
                }
            }
            part -= __logf(prod);
        }
    }
    #pragma unroll
    for (int o = 16; o > 0; o >>= 1)
        part += __shfl_down_sync(0xffffffffu, part, o);
    if (lane == 0) warp_red[warp] = part;
    __syncthreads();
    if (tid == 0) {
        float tot = 0.0f;
        #pragma unroll
        for (int w = 0; w < 8; w++) tot += warp_red[w];
        atomicAdd(&g_acc[0], (double)tot);
        __threadfence();
        int ticket = atomicAdd(&g_cnt, 1);
        if (ticket == DEC_GRID - 1) {
            g_cnt = 0;
            double NSd = (double)NS_;
            double L1   = g_acc[0] - 0.5 * (double)YD_ * LOG2PI * NSd;
            double L234 = g_acc[1] + 0.5 * (double)XD_ * LOG2PI * NSd;
            double totl = (L1 + L234) / (double)S_ + g_acc[2];
            out[0] = (float)(-totl);
        }
    }
}

extern "C" void kernel_launch(void* const* d_in, const int* in_sizes, int n_in,
                              void* d_out, int out_size)
{
    const float* Y            = (const float*)d_in[0];
    const float* We_mu        = (const float*)d_in[1];
    const float* be_mu        = (const float*)d_in[2];
    const float* We_sig       = (const float*)d_in[3];
    const float* be_sig       = (const float*)d_in[4];
    const float* Wd_mu        = (const float*)d_in[5];
    const float* bd_mu        = (const float*)d_in[6];
    const float* Wd_sig       = (const float*)d_in[7];
    const float* bd_sig       = (const float*)d_in[8];
    const float* phi_mus      = (const float*)d_in[9];
    const float* phi_sigs     = (const float*)d_in[10];
    const float* phi_logits   = (const float*)d_in[11];
    const float* theta_mus    = (const float*)d_in[12];
    const float* theta_sigs   = (const float*)d_in[13];
    const float* theta_logits = (const float*)d_in[14];
    const float* u_noise      = (const float*)d_in[15];
    const float* eps_noise    = (const float*)d_in[16];
    const float* temperature  = (const float*)d_in[17];

    encoder_kernel<<<N_ / 32, 256>>>(Y, We_mu, be_mu, We_sig, be_sig);
    mixture_kernel<<<N_ / 2, 128>>>(phi_mus, phi_sigs, phi_logits,
                                    theta_mus, theta_sigs, theta_logits,
                                    u_noise, eps_noise, temperature);
    decoder_kernel<<<dim3(NS_ / DBM, YD_ / 64), 256>>>(Y, Wd_mu, bd_mu,
                                                       Wd_sig, bd_sig,
                                                       (float*)d_out);
}